// round 4
// baseline (speedup 1.0000x reference)
#include <cuda_runtime.h>

#define Dd     3
#define HID    64
#define WIDTH  64
#define BATCH  500000
#define BLOCKP (Dd * WIDTH)         // 192
#define P3N    (3 * BLOCKP + WIDTH) // 640

#define TPB    256
#define EPT    4                     // 2 f32x2 pairs per thread
#define NPAIR  2
#define NCNF   489                   // ceil(BATCH / (TPB*EPT))
#define NBLK   (NCNF + 1)            // +1 hypernet block

typedef unsigned long long ull;

// Params, packed-duplicated for f32x2 math. Per hidden unit j, 4 float4s:
//  [4j+0] = {W0,W0,W1,W1}
//  [4j+1] = {W2,W2,B,B}
//  [4j+2] = {U0/64,U0/64,U1/64,U1/64}
//  [4j+3] = {U2/64,U2/64,wu/64,wu/64}
__device__ float4   g_p4[4 * WIDTH];
__device__ float    g_S;             // sum_j wu[j] / 64
__device__ unsigned g_flag = 0;      // params-ready flag
__device__ unsigned g_done = 0;      // blocks-past-spin counter

// ---------------------------------------------------------------------------
// helpers
// ---------------------------------------------------------------------------
__device__ __forceinline__ ull ffma2(ull a, ull b, ull c) {
    ull d;
    asm("fma.rn.f32x2 %0, %1, %2, %3;" : "=l"(d) : "l"(a), "l"(b), "l"(c));
    return d;
}
__device__ __forceinline__ ull fmul2(ull a, ull b) {
    ull d;
    asm("mul.rn.f32x2 %0, %1, %2;" : "=l"(d) : "l"(a), "l"(b));
    return d;
}
__device__ __forceinline__ ull pack2(float lo, float hi) {
    ull d;
    asm("mov.b64 %0, {%1, %2};" : "=l"(d) : "f"(lo), "f"(hi));
    return d;
}
__device__ __forceinline__ void unpack2(ull v, float& lo, float& hi) {
    asm("mov.b64 {%0, %1}, %2;" : "=f"(lo), "=f"(hi) : "l"(v));
}
__device__ __forceinline__ float tanha(float x) {
    float r;
    asm("tanh.approx.f32 %0, %1;" : "=f"(r) : "f"(x));
    return r;
}

// ---------------------------------------------------------------------------
// Fused kernel. Block 0: hypernet producer. Blocks 1..NCNF: batch consumers.
// ---------------------------------------------------------------------------
__global__ void __launch_bounds__(TPB, 4)
fused_kernel(const float* __restrict__ z, float* __restrict__ out,
             const float* __restrict__ t,
             const float* __restrict__ fc1_w,
             const float* __restrict__ fc1_b,
             const float* __restrict__ fc2_w,
             const float* __restrict__ fc2_b,
             const float* __restrict__ fc3_w,
             const float* __restrict__ fc3_b)
{
    const int tid = threadIdx.x;
    const int bx  = blockIdx.x;

    if (bx == 0) {
        // ---------------- hypernet producer ----------------
        __shared__ float p1[HID];
        __shared__ float p2[HID];
        __shared__ float p3[P3N];
        __shared__ float swu[WIDTH];

        // stage 1
        if (tid < HID) {
            p1[tid] = tanhf(t[0] * fc1_w[tid] + fc1_b[tid]);
        }
        __syncthreads();

        // stage 2
        if (tid < HID) {
            const float4* row = reinterpret_cast<const float4*>(fc2_w + tid * HID);
            float a0 = 0.f, a1 = 0.f, a2 = 0.f, a3 = 0.f;
            #pragma unroll
            for (int i = 0; i < 16; i++) {
                float4 r = row[i];
                const float* pp = p1 + 4 * i;
                a0 = fmaf(r.x, pp[0], a0);
                a1 = fmaf(r.y, pp[1], a1);
                a2 = fmaf(r.z, pp[2], a2);
                a3 = fmaf(r.w, pp[3], a3);
            }
            p2[tid] = tanhf((a0 + a1) + (a2 + a3) + fc2_b[tid]);
        }
        __syncthreads();

        // stage 3: 640 rows across 256 threads (2-3 rows each)
        for (int grow = tid; grow < P3N; grow += TPB) {
            const float4* row = reinterpret_cast<const float4*>(fc3_w + grow * HID);
            float a0 = 0.f, a1 = 0.f, a2 = 0.f, a3 = 0.f;
            #pragma unroll
            for (int i = 0; i < 16; i++) {
                float4 r = row[i];
                const float* pp = p2 + 4 * i;
                a0 = fmaf(r.x, pp[0], a0);
                a1 = fmaf(r.y, pp[1], a1);
                a2 = fmaf(r.z, pp[2], a2);
                a3 = fmaf(r.w, pp[3], a3);
            }
            p3[grow] = (a0 + a1) + (a2 + a3) + fc3_b[grow];
        }
        __syncthreads();

        // assemble; fold 1/WIDTH into U and wu
        const float inv = 1.0f / (float)WIDTH;
        if (tid < WIDTH) {
            const int j = tid;
            float w[3], u[3];
            #pragma unroll
            for (int d = 0; d < 3; d++) {
                w[d] = p3[3 * j + d];
                float ur = p3[BLOCKP + 3 * j + d];
                float g  = p3[2 * BLOCKP + 3 * j + d];
                float sg = 1.0f / (1.0f + expf(-g));
                u[d] = ur * sg * inv;
            }
            float wu = fmaf(w[0], u[0], fmaf(w[1], u[1], w[2] * u[2]));
            float bb = p3[3 * BLOCKP + j];
            g_p4[4 * j + 0] = make_float4(w[0], w[0], w[1], w[1]);
            g_p4[4 * j + 1] = make_float4(w[2], w[2], bb,  bb);
            g_p4[4 * j + 2] = make_float4(u[0], u[0], u[1], u[1]);
            g_p4[4 * j + 3] = make_float4(u[2], u[2], wu,  wu);
            swu[j] = wu;
        }
        __syncthreads();

        if (tid == 0) {
            float s = 0.0f;
            #pragma unroll
            for (int j = 0; j < WIDTH; j++) s += swu[j];
            g_S = s;
            __threadfence();                 // params visible before flag
            atomicExch(&g_flag, 1u);
            // block 0 counts itself as past-the-spin
            unsigned c = atomicAdd(&g_done, 1u);
            if (c == NBLK - 1) { g_flag = 0u; __threadfence(); g_done = 0u; }
        }
        return;
    }

    // ---------------- batch consumer ----------------
    __shared__ __align__(16) float4 sp4[4 * WIDTH];
    __shared__ float sS;

    const int base = ((bx - 1) * TPB + tid) * EPT;
    const bool active = (base < BATCH);     // BATCH % 4 == 0: all-or-nothing

    // preload z BEFORE waiting on params (overlaps with hypernet)
    float4 a0, a1, a2;
    if (active) {
        const float4* z4 = reinterpret_cast<const float4*>(z + (size_t)base * 3);
        a0 = z4[0]; a1 = z4[1]; a2 = z4[2];
    }

    // spin-wait for params (one thread polls), then acquire
    if (tid == 0) {
        while (*(volatile unsigned*)&g_flag == 0u) __nanosleep(64);
        __threadfence();
        unsigned c = atomicAdd(&g_done, 1u);
        if (c == NBLK - 1) { g_flag = 0u; __threadfence(); g_done = 0u; }
    }
    __syncthreads();

    // params global -> shared (256 entries, one per thread)
    sp4[tid] = g_p4[tid];
    if (tid == 0) sS = g_S;
    __syncthreads();

    if (!active) return;

    const float S = sS;

    // pack z into f32x2 pairs: pair p = elements {2p, 2p+1}
    float f[12];
    f[0] = a0.x; f[1]  = a0.y; f[2]  = a0.z; f[3]  = a0.w;
    f[4] = a1.x; f[5]  = a1.y; f[6]  = a1.z; f[7]  = a1.w;
    f[8] = a2.x; f[9]  = a2.y; f[10] = a2.z; f[11] = a2.w;

    ull zx2[NPAIR], zy2[NPAIR], zz2[NPAIR];
    #pragma unroll
    for (int p = 0; p < NPAIR; p++) {
        zx2[p] = pack2(f[6 * p + 0], f[6 * p + 3]);
        zy2[p] = pack2(f[6 * p + 1], f[6 * p + 4]);
        zz2[p] = pack2(f[6 * p + 2], f[6 * p + 5]);
    }

    ull d0[NPAIR], d1[NPAIR], d2[NPAIR], hw[NPAIR];
    #pragma unroll
    for (int p = 0; p < NPAIR; p++) { d0[p] = 0; d1[p] = 0; d2[p] = 0; hw[p] = 0; }

    const ulonglong2* spp = reinterpret_cast<const ulonglong2*>(sp4);

    #pragma unroll 8
    for (int j = 0; j < WIDTH; j++) {
        const ulonglong2 q0 = spp[4 * j + 0];  // {W0,W0},{W1,W1}
        const ulonglong2 q1 = spp[4 * j + 1];  // {W2,W2},{B,B}
        const ulonglong2 q2 = spp[4 * j + 2];  // {U0',U0'},{U1',U1'}
        const ulonglong2 q3 = spp[4 * j + 3];  // {U2',U2'},{wu',wu'}
        #pragma unroll
        for (int p = 0; p < NPAIR; p++) {
            ull pre = ffma2(zz2[p], q1.x, q1.y);
            pre = ffma2(zy2[p], q0.y, pre);
            pre = ffma2(zx2[p], q0.x, pre);
            float plo, phi;
            unpack2(pre, plo, phi);
            ull h2 = pack2(tanha(plo), tanha(phi));
            d0[p] = ffma2(h2, q2.x, d0[p]);
            d1[p] = ffma2(h2, q2.y, d1[p]);
            d2[p] = ffma2(h2, q3.x, d2[p]);
            ull hh = fmul2(h2, h2);
            hw[p] = ffma2(hh, q3.y, hw[p]);
        }
    }

    // epilogue: /WIDTH already folded into U', wu'
    float od[12], lp[4];
    #pragma unroll
    for (int p = 0; p < NPAIR; p++) {
        float a, b;
        unpack2(d0[p], a, b); od[6 * p + 0] = a; od[6 * p + 3] = b;
        unpack2(d1[p], a, b); od[6 * p + 1] = a; od[6 * p + 4] = b;
        unpack2(d2[p], a, b); od[6 * p + 2] = a; od[6 * p + 5] = b;
        unpack2(hw[p], a, b);
        lp[2 * p + 0] = a - S;
        lp[2 * p + 1] = b - S;
    }

    float4* o = reinterpret_cast<float4*>(out + (size_t)base * 3);
    o[0] = make_float4(od[0], od[1], od[2],  od[3]);
    o[1] = make_float4(od[4], od[5], od[6],  od[7]);
    o[2] = make_float4(od[8], od[9], od[10], od[11]);

    *reinterpret_cast<float4*>(out + (size_t)(3 * BATCH) + base) =
        make_float4(lp[0], lp[1], lp[2], lp[3]);
}

// ---------------------------------------------------------------------------
// Launch
// ---------------------------------------------------------------------------
extern "C" void kernel_launch(void* const* d_in, const int* in_sizes, int n_in,
                              void* d_out, int out_size)
{
    const float* t     = (const float*)d_in[0];
    const float* z     = (const float*)d_in[1];
    // d_in[2] = logp_z (unused)
    const float* fc1_w = (const float*)d_in[3];
    const float* fc1_b = (const float*)d_in[4];
    const float* fc2_w = (const float*)d_in[5];
    const float* fc2_b = (const float*)d_in[6];
    const float* fc3_w = (const float*)d_in[7];
    const float* fc3_b = (const float*)d_in[8];
    float* out = (float*)d_out;

    fused_kernel<<<NBLK, TPB>>>(z, out, t, fc1_w, fc1_b, fc2_w, fc2_b,
                                fc3_w, fc3_b);
}

// round 6
// speedup vs baseline: 1.0820x; 1.0820x over previous
#include <cuda_runtime.h>

#define Dd     3
#define HID    64
#define WIDTH  64
#define BATCH  500000
#define BLOCKP (Dd * WIDTH)         // 192
#define P3N    (3 * BLOCKP + WIDTH) // 640

#define TPB    128
#define EPT    4                     // 2 f32x2 pairs per thread
#define NPAIR  2

typedef unsigned long long ull;

// Params, packed-duplicated for f32x2 math. Per hidden unit j, 4 float4s:
//  [4j+0] = {W0,W0,W1,W1}
//  [4j+1] = {W2,W2,B,B}
//  [4j+2] = {U0/64,U0/64,U1/64,U1/64}
//  [4j+3] = {U2/64,U2/64,wu/64,wu/64}
__device__ float4 g_p4[4 * WIDTH];
__device__ float  g_S;               // sum_j wu[j]/64

// ---------------------------------------------------------------------------
// helpers
// ---------------------------------------------------------------------------
__device__ __forceinline__ ull ffma2(ull a, ull b, ull c) {
    ull d;
    asm("fma.rn.f32x2 %0, %1, %2, %3;" : "=l"(d) : "l"(a), "l"(b), "l"(c));
    return d;
}
__device__ __forceinline__ ull fmul2(ull a, ull b) {
    ull d;
    asm("mul.rn.f32x2 %0, %1, %2;" : "=l"(d) : "l"(a), "l"(b));
    return d;
}
__device__ __forceinline__ ull pack2(float lo, float hi) {
    ull d;
    asm("mov.b64 %0, {%1, %2};" : "=l"(d) : "f"(lo), "f"(hi));
    return d;
}
__device__ __forceinline__ void unpack2(ull v, float& lo, float& hi) {
    asm("mov.b64 {%0, %1}, %2;" : "=f"(lo), "=f"(hi) : "l"(v));
}
__device__ __forceinline__ float tanha(float x) {
    float r;
    asm("tanh.approx.f32 %0, %1;" : "=f"(r) : "f"(x));
    return r;
}

// ---------------------------------------------------------------------------
// Kernel 1: hypernet, 4 blocks. Block b produces j in [16b, 16b+16).
// ---------------------------------------------------------------------------
__global__ void __launch_bounds__(256)
hyper_kernel(const float* __restrict__ t,
             const float* __restrict__ fc1_w,
             const float* __restrict__ fc1_b,
             const float* __restrict__ fc2_w,
             const float* __restrict__ fc2_b,
             const float* __restrict__ fc3_w,
             const float* __restrict__ fc3_b)
{
    __shared__ float p1[HID];
    __shared__ float p2[HID];
    __shared__ float p3loc[160];
    __shared__ float swu[WIDTH];

    const int tid = threadIdx.x;
    const int b   = blockIdx.x;

    // stage 1
    if (tid < HID) {
        p1[tid] = tanhf(t[0] * fc1_w[tid] + fc1_b[tid]);
    }
    __syncthreads();

    // stage 2
    if (tid < HID) {
        const float4* row = reinterpret_cast<const float4*>(fc2_w + tid * HID);
        float a0 = 0.f, a1 = 0.f, a2 = 0.f, a3 = 0.f;
        #pragma unroll
        for (int i = 0; i < 16; i++) {
            float4 r = row[i];
            const float* pp = p1 + 4 * i;
            a0 = fmaf(r.x, pp[0], a0);
            a1 = fmaf(r.y, pp[1], a1);
            a2 = fmaf(r.z, pp[2], a2);
            a3 = fmaf(r.w, pp[3], a3);
        }
        p2[tid] = tanhf((a0 + a1) + (a2 + a3) + fc2_b[tid]);
    }
    __syncthreads();

    // stage 3: the 160 fc3 rows this block's j-slice needs.
    if (tid < 160) {
        int grow;
        if      (tid < 48)  grow = 48 * b + tid;
        else if (tid < 96)  grow = BLOCKP + 48 * b + (tid - 48);
        else if (tid < 144) grow = 2 * BLOCKP + 48 * b + (tid - 96);
        else                grow = 3 * BLOCKP + 16 * b + (tid - 144);

        const float4* row = reinterpret_cast<const float4*>(fc3_w + grow * HID);
        float a0 = 0.f, a1 = 0.f, a2 = 0.f, a3 = 0.f;
        #pragma unroll
        for (int i = 0; i < 16; i++) {
            float4 r = row[i];
            const float* pp = p2 + 4 * i;
            a0 = fmaf(r.x, pp[0], a0);
            a1 = fmaf(r.y, pp[1], a1);
            a2 = fmaf(r.z, pp[2], a2);
            a3 = fmaf(r.w, pp[3], a3);
        }
        p3loc[tid] = (a0 + a1) + (a2 + a3) + fc3_b[grow];
    }
    __syncthreads();

    // assemble this block's 16 j's; fold 1/WIDTH into U and wu
    const float inv = 1.0f / (float)WIDTH;
    if (tid < 16) {
        const int j = 16 * b + tid;
        float w[3], u[3];
        #pragma unroll
        for (int d = 0; d < 3; d++) {
            w[d] = p3loc[3 * tid + d];
            float ur = p3loc[48 + 3 * tid + d];
            float g  = p3loc[96 + 3 * tid + d];
            float sg = 1.0f / (1.0f + expf(-g));
            u[d] = ur * sg * inv;
        }
        float wu = fmaf(w[0], u[0], fmaf(w[1], u[1], w[2] * u[2]));
        float bb = p3loc[144 + tid];
        g_p4[4 * j + 0] = make_float4(w[0], w[0], w[1], w[1]);
        g_p4[4 * j + 1] = make_float4(w[2], w[2], bb,  bb);
        g_p4[4 * j + 2] = make_float4(u[0], u[0], u[1], u[1]);
        g_p4[4 * j + 3] = make_float4(u[2], u[2], wu,  wu);
        swu[tid] = wu;
    }
    __syncthreads();

    // block 0 also publishes S = sum wu/64 (sums its own slice? no — needs all).
    // Compute S redundantly per block from its 16 wu's via atomic? Simpler:
    // each block writes partial sums is racy across blocks. Instead block b
    // sums ITS 16 and atomically adds into g_S — but g_S must be zeroed each
    // replay. Use deterministic: block 0 cannot see other blocks' wu.
    // => compute S in cnf from sp4 instead (cheap: 64 adds once per block).
    (void)swu;
}

// ---------------------------------------------------------------------------
// Kernel 2: main batch kernel. 4 elements/thread as 2 f32x2 pairs.
// ---------------------------------------------------------------------------
__global__ void __launch_bounds__(TPB)
cnf_kernel(const float* __restrict__ z, float* __restrict__ out)
{
    __shared__ __align__(16) float4 sp4[4 * WIDTH];
    __shared__ float sS;

    const int tid = threadIdx.x;
    #pragma unroll
    for (int i = tid; i < 4 * WIDTH; i += TPB) sp4[i] = g_p4[i];
    __syncthreads();

    // S = sum_j wu'/64 — one warp computes it once per block (broadcast LDS)
    if (tid < 32) {
        float s = 0.f;
        // wu' lives at sp4[4j+3].z (== .w); lane l sums j = l, l+32
        s += sp4[4 * tid + 3].z;
        s += sp4[4 * (tid + 32) + 3].z;
        #pragma unroll
        for (int off = 16; off > 0; off >>= 1)
            s += __shfl_xor_sync(0xffffffffu, s, off);
        if (tid == 0) sS = s;
    }
    __syncthreads();
    const float S = sS;

    const int base = (blockIdx.x * TPB + tid) * EPT;
    if (base >= BATCH) return;   // BATCH % 4 == 0

    const float4* z4 = reinterpret_cast<const float4*>(z + (size_t)base * 3);
    float4 a0 = z4[0], a1 = z4[1], a2 = z4[2];

    // pack into f32x2 pairs: pair0 = elems {0,1}, pair1 = elems {2,3}
    ull zx2[NPAIR], zy2[NPAIR], zz2[NPAIR];
    zx2[0] = pack2(a0.x, a0.w);
    zy2[0] = pack2(a0.y, a1.x);
    zz2[0] = pack2(a0.z, a1.y);
    zx2[1] = pack2(a1.z, a2.y);
    zy2[1] = pack2(a1.w, a2.z);
    zz2[1] = pack2(a2.x, a2.w);

    ull d0[NPAIR], d1[NPAIR], d2[NPAIR], hw[NPAIR];
    #pragma unroll
    for (int p = 0; p < NPAIR; p++) { d0[p] = 0; d1[p] = 0; d2[p] = 0; hw[p] = 0; }

    const ulonglong2* spp = reinterpret_cast<const ulonglong2*>(sp4);

    #pragma unroll 8
    for (int j = 0; j < WIDTH; j++) {
        const ulonglong2 q0 = spp[4 * j + 0];  // {W0,W0},{W1,W1}
        const ulonglong2 q1 = spp[4 * j + 1];  // {W2,W2},{B,B}
        const ulonglong2 q2 = spp[4 * j + 2];  // {U0',U0'},{U1',U1'}
        const ulonglong2 q3 = spp[4 * j + 3];  // {U2',U2'},{wu',wu'}
        #pragma unroll
        for (int p = 0; p < NPAIR; p++) {
            ull pre = ffma2(zz2[p], q1.x, q1.y);
            pre = ffma2(zy2[p], q0.y, pre);
            pre = ffma2(zx2[p], q0.x, pre);
            float plo, phi;
            unpack2(pre, plo, phi);
            ull h2 = pack2(tanha(plo), tanha(phi));
            d0[p] = ffma2(h2, q2.x, d0[p]);
            d1[p] = ffma2(h2, q2.y, d1[p]);
            d2[p] = ffma2(h2, q3.x, d2[p]);
            ull hh = fmul2(h2, h2);
            hw[p] = ffma2(hh, q3.y, hw[p]);
        }
    }

    // epilogue (/WIDTH already folded)
    float od[12], lp[4];
    #pragma unroll
    for (int p = 0; p < NPAIR; p++) {
        float a, b;
        unpack2(d0[p], a, b); od[6 * p + 0] = a; od[6 * p + 3] = b;
        unpack2(d1[p], a, b); od[6 * p + 1] = a; od[6 * p + 4] = b;
        unpack2(d2[p], a, b); od[6 * p + 2] = a; od[6 * p + 5] = b;
        unpack2(hw[p], a, b);
        lp[2 * p + 0] = a - S;
        lp[2 * p + 1] = b - S;
    }

    float4* o = reinterpret_cast<float4*>(out + (size_t)base * 3);
    o[0] = make_float4(od[0], od[1], od[2],  od[3]);
    o[1] = make_float4(od[4], od[5], od[6],  od[7]);
    o[2] = make_float4(od[8], od[9], od[10], od[11]);

    *reinterpret_cast<float4*>(out + (size_t)(3 * BATCH) + base) =
        make_float4(lp[0], lp[1], lp[2], lp[3]);
}

// ---------------------------------------------------------------------------
// Launch
// ---------------------------------------------------------------------------
extern "C" void kernel_launch(void* const* d_in, const int* in_sizes, int n_in,
                              void* d_out, int out_size)
{
    const float* t     = (const float*)d_in[0];
    const float* z     = (const float*)d_in[1];
    // d_in[2] = logp_z (unused)
    const float* fc1_w = (const float*)d_in[3];
    const float* fc1_b = (const float*)d_in[4];
    const float* fc2_w = (const float*)d_in[5];
    const float* fc2_b = (const float*)d_in[6];
    const float* fc3_w = (const float*)d_in[7];
    const float* fc3_b = (const float*)d_in[8];
    float* out = (float*)d_out;

    hyper_kernel<<<4, 256>>>(t, fc1_w, fc1_b, fc2_w, fc2_b, fc3_w, fc3_b);

    const int elems_per_block = TPB * EPT;                            // 512
    const int grid = (BATCH + elems_per_block - 1) / elems_per_block; // 977
    cnf_kernel<<<grid, TPB>>>(z, out);
}

// round 7
// speedup vs baseline: 1.2299x; 1.1367x over previous
#include <cuda_runtime.h>

#define Dd     3
#define HID    64
#define WIDTH  64
#define BATCH  500000
#define BLOCKP (Dd * WIDTH)         // 192
#define P3N    (3 * BLOCKP + WIDTH) // 640

#define TPB    256
#define EPT    2                     // 1 f32x2 pair per thread
#define NTHREADS (BATCH / EPT)       // 250000
#define GRID   ((NTHREADS + TPB - 1) / TPB)   // 977

typedef unsigned long long ull;

// Params, packed-duplicated for f32x2 math. Per hidden unit j, 4 float4s:
//  [4j+0] = {W0,W0,W1,W1}
//  [4j+1] = {W2,W2,B,B}
//  [4j+2] = {U0/64,U0/64,U1/64,U1/64}
//  [4j+3] = {U2/64,U2/64,wu/64,wu/64}
__device__ float4 g_p4[4 * WIDTH];

// ---------------------------------------------------------------------------
// helpers
// ---------------------------------------------------------------------------
__device__ __forceinline__ ull ffma2(ull a, ull b, ull c) {
    ull d;
    asm("fma.rn.f32x2 %0, %1, %2, %3;" : "=l"(d) : "l"(a), "l"(b), "l"(c));
    return d;
}
__device__ __forceinline__ ull fmul2(ull a, ull b) {
    ull d;
    asm("mul.rn.f32x2 %0, %1, %2;" : "=l"(d) : "l"(a), "l"(b));
    return d;
}
__device__ __forceinline__ ull pack2(float lo, float hi) {
    ull d;
    asm("mov.b64 %0, {%1, %2};" : "=l"(d) : "f"(lo), "f"(hi));
    return d;
}
__device__ __forceinline__ void unpack2(ull v, float& lo, float& hi) {
    asm("mov.b64 {%0, %1}, %2;" : "=f"(lo), "=f"(hi) : "l"(v));
}
__device__ __forceinline__ float tanha(float x) {
    float r;
    asm("tanh.approx.f32 %0, %1;" : "=f"(r) : "f"(x));
    return r;
}

// ---------------------------------------------------------------------------
// Kernel 1: hypernet, 4 blocks. Block b produces j in [16b, 16b+16).
// Triggers programmatic launch completion immediately so cnf_kernel can
// launch and preload z concurrently.
// ---------------------------------------------------------------------------
__global__ void __launch_bounds__(256)
hyper_kernel(const float* __restrict__ t,
             const float* __restrict__ fc1_w,
             const float* __restrict__ fc1_b,
             const float* __restrict__ fc2_w,
             const float* __restrict__ fc2_b,
             const float* __restrict__ fc3_w,
             const float* __restrict__ fc3_b)
{
#if __CUDA_ARCH__ >= 900
    cudaTriggerProgrammaticLaunchCompletion();
#endif

    __shared__ float p1[HID];
    __shared__ float p2[HID];
    __shared__ float p3loc[160];

    const int tid = threadIdx.x;
    const int b   = blockIdx.x;

    // stage 1
    if (tid < HID) {
        p1[tid] = tanhf(t[0] * fc1_w[tid] + fc1_b[tid]);
    }
    __syncthreads();

    // stage 2
    if (tid < HID) {
        const float4* row = reinterpret_cast<const float4*>(fc2_w + tid * HID);
        float a0 = 0.f, a1 = 0.f, a2 = 0.f, a3 = 0.f;
        #pragma unroll
        for (int i = 0; i < 16; i++) {
            float4 r = row[i];
            const float* pp = p1 + 4 * i;
            a0 = fmaf(r.x, pp[0], a0);
            a1 = fmaf(r.y, pp[1], a1);
            a2 = fmaf(r.z, pp[2], a2);
            a3 = fmaf(r.w, pp[3], a3);
        }
        p2[tid] = tanhf((a0 + a1) + (a2 + a3) + fc2_b[tid]);
    }
    __syncthreads();

    // stage 3: the 160 fc3 rows this block's j-slice needs.
    if (tid < 160) {
        int grow;
        if      (tid < 48)  grow = 48 * b + tid;
        else if (tid < 96)  grow = BLOCKP + 48 * b + (tid - 48);
        else if (tid < 144) grow = 2 * BLOCKP + 48 * b + (tid - 96);
        else                grow = 3 * BLOCKP + 16 * b + (tid - 144);

        const float4* row = reinterpret_cast<const float4*>(fc3_w + grow * HID);
        float a0 = 0.f, a1 = 0.f, a2 = 0.f, a3 = 0.f;
        #pragma unroll
        for (int i = 0; i < 16; i++) {
            float4 r = row[i];
            const float* pp = p2 + 4 * i;
            a0 = fmaf(r.x, pp[0], a0);
            a1 = fmaf(r.y, pp[1], a1);
            a2 = fmaf(r.z, pp[2], a2);
            a3 = fmaf(r.w, pp[3], a3);
        }
        p3loc[tid] = (a0 + a1) + (a2 + a3) + fc3_b[grow];
    }
    __syncthreads();

    // assemble this block's 16 j's; fold 1/WIDTH into U and wu
    const float inv = 1.0f / (float)WIDTH;
    if (tid < 16) {
        const int j = 16 * b + tid;
        float w[3], u[3];
        #pragma unroll
        for (int d = 0; d < 3; d++) {
            w[d] = p3loc[3 * tid + d];
            float ur = p3loc[48 + 3 * tid + d];
            float g  = p3loc[96 + 3 * tid + d];
            float sg = 1.0f / (1.0f + expf(-g));
            u[d] = ur * sg * inv;
        }
        float wu = fmaf(w[0], u[0], fmaf(w[1], u[1], w[2] * u[2]));
        float bb = p3loc[144 + tid];
        g_p4[4 * j + 0] = make_float4(w[0], w[0], w[1], w[1]);
        g_p4[4 * j + 1] = make_float4(w[2], w[2], bb,  bb);
        g_p4[4 * j + 2] = make_float4(u[0], u[0], u[1], u[1]);
        g_p4[4 * j + 3] = make_float4(u[2], u[2], wu,  wu);
    }
}

// ---------------------------------------------------------------------------
// Kernel 2: main batch kernel. 2 elements/thread = 1 f32x2 pair.
// Launched with programmatic stream serialization: preloads z, then waits
// for hyper_kernel's grid to complete before reading g_p4.
// ---------------------------------------------------------------------------
__global__ void __launch_bounds__(TPB)
cnf_kernel(const float* __restrict__ z, float* __restrict__ out)
{
    __shared__ __align__(16) float4 sp4[4 * WIDTH];
    __shared__ float sS;

    const int tid  = threadIdx.x;
    const int gtid = blockIdx.x * TPB + tid;
    const int base = gtid * EPT;
    const bool active = (base < BATCH);   // BATCH % 2 == 0

    // preload z while hyper_kernel still runs (6 floats, 8B-aligned)
    float2 l0, l1, l2;
    if (active) {
        const float2* z2 = reinterpret_cast<const float2*>(z + (size_t)base * 3);
        l0 = z2[0]; l1 = z2[1]; l2 = z2[2];
    }

#if __CUDA_ARCH__ >= 900
    cudaGridDependencySynchronize();
#endif

    // params global -> shared (256 entries, one per thread)
    sp4[tid] = g_p4[tid];
    __syncthreads();

    // S = sum_j wu'/64 — warp 0 computes once per block
    if (tid < 32) {
        float s = sp4[4 * tid + 3].z + sp4[4 * (tid + 32) + 3].z;
        #pragma unroll
        for (int off = 16; off > 0; off >>= 1)
            s += __shfl_xor_sync(0xffffffffu, s, off);
        if (tid == 0) sS = s;
    }
    __syncthreads();

    if (!active) return;
    const float S = sS;

    // pack: lane0 = elem0 = (l0.x,l0.y,l1.x), lane1 = elem1 = (l1.y,l2.x,l2.y)
    ull zx2 = pack2(l0.x, l1.y);
    ull zy2 = pack2(l0.y, l2.x);
    ull zz2 = pack2(l1.x, l2.y);

    ull d0 = 0, d1 = 0, d2 = 0, hw = 0;

    const ulonglong2* spp = reinterpret_cast<const ulonglong2*>(sp4);

    #pragma unroll 8
    for (int j = 0; j < WIDTH; j++) {
        const ulonglong2 q0 = spp[4 * j + 0];  // {W0,W0},{W1,W1}
        const ulonglong2 q1 = spp[4 * j + 1];  // {W2,W2},{B,B}
        const ulonglong2 q2 = spp[4 * j + 2];  // {U0',U0'},{U1',U1'}
        const ulonglong2 q3 = spp[4 * j + 3];  // {U2',U2'},{wu',wu'}
        ull pre = ffma2(zz2, q1.x, q1.y);
        pre = ffma2(zy2, q0.y, pre);
        pre = ffma2(zx2, q0.x, pre);
        float plo, phi;
        unpack2(pre, plo, phi);
        ull h2 = pack2(tanha(plo), tanha(phi));
        d0 = ffma2(h2, q2.x, d0);
        d1 = ffma2(h2, q2.y, d1);
        d2 = ffma2(h2, q3.x, d2);
        ull hh = fmul2(h2, h2);
        hw = ffma2(hh, q3.y, hw);
    }

    // epilogue (/WIDTH already folded into params)
    float d0a, d0b, d1a, d1b, d2a, d2b, ha, hb;
    unpack2(d0, d0a, d0b);
    unpack2(d1, d1a, d1b);
    unpack2(d2, d2a, d2b);
    unpack2(hw, ha, hb);

    float2* o = reinterpret_cast<float2*>(out + (size_t)base * 3);
    o[0] = make_float2(d0a, d1a);
    o[1] = make_float2(d2a, d0b);
    o[2] = make_float2(d1b, d2b);

    *reinterpret_cast<float2*>(out + (size_t)(3 * BATCH) + base) =
        make_float2(ha - S, hb - S);
}

// ---------------------------------------------------------------------------
// Launch: hyper, then cnf with programmatic stream serialization (PDL).
// ---------------------------------------------------------------------------
extern "C" void kernel_launch(void* const* d_in, const int* in_sizes, int n_in,
                              void* d_out, int out_size)
{
    const float* t     = (const float*)d_in[0];
    const float* z     = (const float*)d_in[1];
    // d_in[2] = logp_z (unused)
    const float* fc1_w = (const float*)d_in[3];
    const float* fc1_b = (const float*)d_in[4];
    const float* fc2_w = (const float*)d_in[5];
    const float* fc2_b = (const float*)d_in[6];
    const float* fc3_w = (const float*)d_in[7];
    const float* fc3_b = (const float*)d_in[8];
    float* out = (float*)d_out;

    hyper_kernel<<<4, 256>>>(t, fc1_w, fc1_b, fc2_w, fc2_b, fc3_w, fc3_b);

    cudaLaunchConfig_t cfg = {};
    cfg.gridDim  = dim3(GRID, 1, 1);
    cfg.blockDim = dim3(TPB, 1, 1);
    cfg.dynamicSmemBytes = 0;
    cudaLaunchAttribute attrs[1];
    attrs[0].id = cudaLaunchAttributeProgrammaticStreamSerialization;
    attrs[0].val.programmaticStreamSerializationAllowed = 1;
    cfg.attrs = attrs;
    cfg.numAttrs = 1;
    cudaLaunchKernelEx(&cfg, cnf_kernel, z, out);
}

// round 8
// speedup vs baseline: 1.4503x; 1.1792x over previous
#include <cuda_runtime.h>

#define Dd     3
#define HID    64
#define WIDTH  64
#define BATCH  500000
#define BLOCKP (Dd * WIDTH)         // 192
#define P3N    (3 * BLOCKP + WIDTH) // 640

#define TPB    128
#define EPT    4                     // 2 f32x2 pairs per thread
#define NPAIR  2
#define GRID   ((BATCH / EPT + TPB - 1) / TPB)   // 977

typedef unsigned long long ull;

// Params, packed-duplicated for f32x2 math. Per hidden unit j, 4 float4s:
//  [4j+0] = {W0,W0,W1,W1}
//  [4j+1] = {W2,W2,B,B}
//  [4j+2] = {U0/64,U0/64,U1/64,U1/64}
//  [4j+3] = {U2/64,U2/64,wu/64,wu/64}
__device__ float4 g_p4[4 * WIDTH];

// ---------------------------------------------------------------------------
// helpers
// ---------------------------------------------------------------------------
__device__ __forceinline__ ull ffma2(ull a, ull b, ull c) {
    ull d;
    asm("fma.rn.f32x2 %0, %1, %2, %3;" : "=l"(d) : "l"(a), "l"(b), "l"(c));
    return d;
}
__device__ __forceinline__ ull fmul2(ull a, ull b) {
    ull d;
    asm("mul.rn.f32x2 %0, %1, %2;" : "=l"(d) : "l"(a), "l"(b));
    return d;
}
__device__ __forceinline__ ull pack2(float lo, float hi) {
    ull d;
    asm("mov.b64 %0, {%1, %2};" : "=l"(d) : "f"(lo), "f"(hi));
    return d;
}
__device__ __forceinline__ void unpack2(ull v, float& lo, float& hi) {
    asm("mov.b64 {%0, %1}, %2;" : "=f"(lo), "=f"(hi) : "l"(v));
}
__device__ __forceinline__ float tanha(float x) {
    float r;
    asm("tanh.approx.f32 %0, %1;" : "=f"(r) : "f"(x));
    return r;
}

// ---------------------------------------------------------------------------
// Kernel 1: hypernet, 4 blocks. Block b produces j in [16b, 16b+16).
// PDL: triggers launch completion immediately so cnf can start concurrently.
// ---------------------------------------------------------------------------
__global__ void __launch_bounds__(256)
hyper_kernel(const float* __restrict__ t,
             const float* __restrict__ fc1_w,
             const float* __restrict__ fc1_b,
             const float* __restrict__ fc2_w,
             const float* __restrict__ fc2_b,
             const float* __restrict__ fc3_w,
             const float* __restrict__ fc3_b)
{
#if __CUDA_ARCH__ >= 900
    cudaTriggerProgrammaticLaunchCompletion();
#endif

    __shared__ float p1[HID];
    __shared__ float p2[HID];
    __shared__ float p3loc[160];

    const int tid = threadIdx.x;
    const int b   = blockIdx.x;

    // stage 1
    if (tid < HID) {
        p1[tid] = tanhf(t[0] * fc1_w[tid] + fc1_b[tid]);
    }
    __syncthreads();

    // stage 2
    if (tid < HID) {
        const float4* row = reinterpret_cast<const float4*>(fc2_w + tid * HID);
        float a0 = 0.f, a1 = 0.f, a2 = 0.f, a3 = 0.f;
        #pragma unroll
        for (int i = 0; i < 16; i++) {
            float4 r = row[i];
            const float* pp = p1 + 4 * i;
            a0 = fmaf(r.x, pp[0], a0);
            a1 = fmaf(r.y, pp[1], a1);
            a2 = fmaf(r.z, pp[2], a2);
            a3 = fmaf(r.w, pp[3], a3);
        }
        p2[tid] = tanhf((a0 + a1) + (a2 + a3) + fc2_b[tid]);
    }
    __syncthreads();

    // stage 3: the 160 fc3 rows this block's j-slice needs.
    if (tid < 160) {
        int grow;
        if      (tid < 48)  grow = 48 * b + tid;
        else if (tid < 96)  grow = BLOCKP + 48 * b + (tid - 48);
        else if (tid < 144) grow = 2 * BLOCKP + 48 * b + (tid - 96);
        else                grow = 3 * BLOCKP + 16 * b + (tid - 144);

        const float4* row = reinterpret_cast<const float4*>(fc3_w + grow * HID);
        float a0 = 0.f, a1 = 0.f, a2 = 0.f, a3 = 0.f;
        #pragma unroll
        for (int i = 0; i < 16; i++) {
            float4 r = row[i];
            const float* pp = p2 + 4 * i;
            a0 = fmaf(r.x, pp[0], a0);
            a1 = fmaf(r.y, pp[1], a1);
            a2 = fmaf(r.z, pp[2], a2);
            a3 = fmaf(r.w, pp[3], a3);
        }
        p3loc[tid] = (a0 + a1) + (a2 + a3) + fc3_b[grow];
    }
    __syncthreads();

    // assemble this block's 16 j's; fold 1/WIDTH into U and wu
    const float inv = 1.0f / (float)WIDTH;
    if (tid < 16) {
        const int j = 16 * b + tid;
        float w[3], u[3];
        #pragma unroll
        for (int d = 0; d < 3; d++) {
            w[d] = p3loc[3 * tid + d];
            float ur = p3loc[48 + 3 * tid + d];
            float g  = p3loc[96 + 3 * tid + d];
            float sg = 1.0f / (1.0f + expf(-g));
            u[d] = ur * sg * inv;
        }
        float wu = fmaf(w[0], u[0], fmaf(w[1], u[1], w[2] * u[2]));
        float bb = p3loc[144 + tid];
        g_p4[4 * j + 0] = make_float4(w[0], w[0], w[1], w[1]);
        g_p4[4 * j + 1] = make_float4(w[2], w[2], bb,  bb);
        g_p4[4 * j + 2] = make_float4(u[0], u[0], u[1], u[1]);
        g_p4[4 * j + 3] = make_float4(u[2], u[2], wu,  wu);
    }
}

// ---------------------------------------------------------------------------
// Kernel 2: main batch kernel. 4 elements/thread = 2 f32x2 pairs.
// PDL consumer: preloads z, then grid-dep-sync before reading g_p4.
// Explicit depth-1 software pipeline on the per-j parameter loads.
// ---------------------------------------------------------------------------
__global__ void __launch_bounds__(TPB, 6)
cnf_kernel(const float* __restrict__ z, float* __restrict__ out)
{
    __shared__ __align__(16) float4 sp4[4 * WIDTH];
    __shared__ float sS;

    const int tid  = threadIdx.x;
    const int base = (blockIdx.x * TPB + tid) * EPT;
    const bool active = (base < BATCH);   // BATCH % 4 == 0: all-or-nothing

    // preload z while hyper_kernel may still be running
    float4 a0, a1, a2;
    if (active) {
        const float4* z4 = reinterpret_cast<const float4*>(z + (size_t)base * 3);
        a0 = z4[0]; a1 = z4[1]; a2 = z4[2];
    }

#if __CUDA_ARCH__ >= 900
    cudaGridDependencySynchronize();
#endif

    // params global -> shared (256 entries, 2 per thread)
    sp4[tid]       = g_p4[tid];
    sp4[tid + TPB] = g_p4[tid + TPB];
    __syncthreads();

    // S = sum_j wu'/64 — warp 0 computes once per block
    if (tid < 32) {
        float s = sp4[4 * tid + 3].z + sp4[4 * (tid + 32) + 3].z;
        #pragma unroll
        for (int off = 16; off > 0; off >>= 1)
            s += __shfl_xor_sync(0xffffffffu, s, off);
        if (tid == 0) sS = s;
    }
    __syncthreads();

    if (!active) return;
    const float S = sS;

    // pack into f32x2 pairs: pair0 = elems {0,1}, pair1 = elems {2,3}
    ull zx2[NPAIR], zy2[NPAIR], zz2[NPAIR];
    zx2[0] = pack2(a0.x, a0.w);
    zy2[0] = pack2(a0.y, a1.x);
    zz2[0] = pack2(a0.z, a1.y);
    zx2[1] = pack2(a1.z, a2.y);
    zy2[1] = pack2(a1.w, a2.z);
    zz2[1] = pack2(a2.x, a2.w);

    ull d0[NPAIR], d1[NPAIR], d2[NPAIR], hw[NPAIR];
    #pragma unroll
    for (int p = 0; p < NPAIR; p++) { d0[p] = 0; d1[p] = 0; d2[p] = 0; hw[p] = 0; }

    const ulonglong2* spp = reinterpret_cast<const ulonglong2*>(sp4);

    // software-pipelined j loop: prefetch j+1 params while computing j
    ulonglong2 c0 = spp[0], c1 = spp[1], c2 = spp[2], c3 = spp[3];

    #pragma unroll 8
    for (int j = 0; j < WIDTH; j++) {
        const int jn = (j + 1) & (WIDTH - 1);
        ulonglong2 n0 = spp[4 * jn + 0];
        ulonglong2 n1 = spp[4 * jn + 1];
        ulonglong2 n2 = spp[4 * jn + 2];
        ulonglong2 n3 = spp[4 * jn + 3];

        #pragma unroll
        for (int p = 0; p < NPAIR; p++) {
            ull pre = ffma2(zz2[p], c1.x, c1.y);
            pre = ffma2(zy2[p], c0.y, pre);
            pre = ffma2(zx2[p], c0.x, pre);
            float plo, phi;
            unpack2(pre, plo, phi);
            ull h2 = pack2(tanha(plo), tanha(phi));
            d0[p] = ffma2(h2, c2.x, d0[p]);
            d1[p] = ffma2(h2, c2.y, d1[p]);
            d2[p] = ffma2(h2, c3.x, d2[p]);
            ull hh = fmul2(h2, h2);
            hw[p] = ffma2(hh, c3.y, hw[p]);
        }

        c0 = n0; c1 = n1; c2 = n2; c3 = n3;
    }

    // epilogue (/WIDTH already folded into params)
    float od[12], lp[4];
    #pragma unroll
    for (int p = 0; p < NPAIR; p++) {
        float a, b;
        unpack2(d0[p], a, b); od[6 * p + 0] = a; od[6 * p + 3] = b;
        unpack2(d1[p], a, b); od[6 * p + 1] = a; od[6 * p + 4] = b;
        unpack2(d2[p], a, b); od[6 * p + 2] = a; od[6 * p + 5] = b;
        unpack2(hw[p], a, b);
        lp[2 * p + 0] = a - S;
        lp[2 * p + 1] = b - S;
    }

    float4* o = reinterpret_cast<float4*>(out + (size_t)base * 3);
    o[0] = make_float4(od[0], od[1], od[2],  od[3]);
    o[1] = make_float4(od[4], od[5], od[6],  od[7]);
    o[2] = make_float4(od[8], od[9], od[10], od[11]);

    *reinterpret_cast<float4*>(out + (size_t)(3 * BATCH) + base) =
        make_float4(lp[0], lp[1], lp[2], lp[3]);
}

// ---------------------------------------------------------------------------
// Launch: hyper, then cnf with programmatic stream serialization (PDL).
// ---------------------------------------------------------------------------
extern "C" void kernel_launch(void* const* d_in, const int* in_sizes, int n_in,
                              void* d_out, int out_size)
{
    const float* t     = (const float*)d_in[0];
    const float* z     = (const float*)d_in[1];
    // d_in[2] = logp_z (unused)
    const float* fc1_w = (const float*)d_in[3];
    const float* fc1_b = (const float*)d_in[4];
    const float* fc2_w = (const float*)d_in[5];
    const float* fc2_b = (const float*)d_in[6];
    const float* fc3_w = (const float*)d_in[7];
    const float* fc3_b = (const float*)d_in[8];
    float* out = (float*)d_out;

    hyper_kernel<<<4, 256>>>(t, fc1_w, fc1_b, fc2_w, fc2_b, fc3_w, fc3_b);

    cudaLaunchConfig_t cfg = {};
    cfg.gridDim  = dim3(GRID, 1, 1);
    cfg.blockDim = dim3(TPB, 1, 1);
    cfg.dynamicSmemBytes = 0;
    cudaLaunchAttribute attrs[1];
    attrs[0].id = cudaLaunchAttributeProgrammaticStreamSerialization;
    attrs[0].val.programmaticStreamSerializationAllowed = 1;
    cfg.attrs = attrs;
    cfg.numAttrs = 1;
    cudaLaunchKernelEx(&cfg, cnf_kernel, z, out);
}